// round 7
// baseline (speedup 1.0000x reference)
#include <cuda_runtime.h>
#include <math.h>

// ---------------------------------------------------------------------------
// Problem dims
// ---------------------------------------------------------------------------
#define NBLK   148
#define NTHR   256
#define GSTRIDE (NBLK * NTHR)
#define Bz     128
#define Sz     512
#define Hz     1024
#define MIDz   512
#define FEATz  576
#define G4Hz   4096
#define KC     16

// Output layout: outs[B,S,H], h2f[1,B,H], c2f[1,B,H], flags[S]
#define OUT_H2    67108864
#define OUT_C2    67239936
#define OUT_FLAGS 67371008

// ---------------------------------------------------------------------------
// Device-global scratch (allocation-free per harness rules)
// ---------------------------------------------------------------------------
__device__ __align__(16) float g_embeds[(size_t)Sz * Bz * FEATz]; // [t][b][f]
__device__ __align__(16) float g_h1[Bz * Hz];
__device__ __align__(16) float g_c1[Bz * Hz];
__device__ __align__(16) float g_h2[Bz * Hz];
__device__ __align__(16) float g_c2[Bz * Hz];
__device__ __align__(16) float g_x2[Bz * Hz];
__device__ __align__(16) float g_zbp[3][Bz * MIDz];
__device__ __align__(16) float g_mx1[Bz * Hz];
__device__ __align__(16) float g_mh1p[2][Bz * Hz];
__device__ __align__(16) float g_zx1[Bz * G4Hz];
__device__ __align__(16) float g_p1p[2][Bz * G4Hz];
__device__ __align__(16) float g_mx2p[3][Bz * Hz];
__device__ __align__(16) float g_mh2p[3][Bz * Hz];
__device__ __align__(16) float g_zx2p[3][Bz * G4Hz];
__device__ __align__(16) float g_p2p[2][Bz * G4Hz];
__device__ __align__(16) float g_s[Bz];
__device__ float g_bdvs;

// grid barrier state (zero-init; gen compared relatively, replay-safe)
__device__ unsigned g_bar_cnt;
__device__ volatile unsigned g_bar_gen;

__device__ __forceinline__ void gridbar() {
    __threadfence();               // release (emits CCTL.IVALL: scope >= cluster)
    __syncthreads();
    if (threadIdx.x == 0) {
        unsigned gen = g_bar_gen;
        if (atomicAdd(&g_bar_cnt, 1u) == (unsigned)(NBLK - 1)) {
            g_bar_cnt = 0u;
            __threadfence();
            g_bar_gen = gen + 1u;
        } else {
            while (g_bar_gen == gen) { __nanosleep(32); }
        }
    }
    __syncthreads();
    __threadfence();               // acquire: flush L1D so plain loads see fresh data
}

// ---------------------------------------------------------------------------
// Packed f32x2 FMA helpers (Blackwell; PTX required — ptxas won't auto-fuse)
// ---------------------------------------------------------------------------
__device__ __forceinline__ void ffma2(unsigned long long &acc,
                                      unsigned long long a,
                                      unsigned long long b) {
    asm("fma.rn.f32x2 %0, %1, %2, %0;" : "+l"(acc) : "l"(a), "l"(b));
}
__device__ __forceinline__ unsigned long long packdup(float x) {
    unsigned int u = __float_as_uint(x);
    unsigned long long r;
    asm("mov.b64 %0, {%1, %1};" : "=l"(r) : "r"(u));
    return r;
}
__device__ __forceinline__ float sigm(float x) { return 1.0f / (1.0f + expf(-x)); }

// ---------------------------------------------------------------------------
// Register-tiled fp32 GEMM tile: C[0:128, 0:64] = A[128,K] @ W[0:64, K]^T
//   A-operand = (sum_{j<NA} Ap[j]) * (NM ? sum_{j<NM} Mp[j] : 1)
// 256 threads, per-thread 4 rows (2 f32x2 pairs) x 8 cols.
// ---------------------------------------------------------------------------
template<int NA, int NM>
__device__ __forceinline__ void gemm_tile(
    const float* const* Ap, const float* const* Mp, int lda,
    const float* __restrict__ W, int ldw, int K,
    float* __restrict__ C, int ldc,
    float (*As)[130], float (*Ws)[68])
{
    const int tid = threadIdx.x;
    const int tx8 = (tid & 7) * 8;
    const int ty4 = (tid >> 3) * 4;

    unsigned long long acc[2][8];
#pragma unroll
    for (int i = 0; i < 2; i++)
#pragma unroll
        for (int j = 0; j < 8; j++) acc[i][j] = 0ull;

    float4 arA[2][NA];
    float4 arM[2][(NM > 0) ? NM : 1];
    float4 wr;

    auto loadA = [&](int k0) {
#pragma unroll
        for (int i = 0; i < 2; i++) {
            int id = i * 256 + tid;
            int r = id >> 2, kq = (id & 3) * 4;
            size_t off = (size_t)r * lda + k0 + kq;
#pragma unroll
            for (int j = 0; j < NA; j++) arA[i][j] = *(const float4*)(Ap[j] + off);
            if constexpr (NM > 0) {
#pragma unroll
                for (int j = 0; j < NM; j++) arM[i][j] = *(const float4*)(Mp[j] + off);
            }
        }
    };
    auto loadW = [&](int k0) {
        int r = tid >> 2, kq = (tid & 3) * 4;
        wr = *(const float4*)(W + (size_t)r * ldw + k0 + kq);
    };

    loadA(0); loadW(0);

    for (int k0 = 0; k0 < K; k0 += KC) {
        // stage regs -> smem (combine sums/products here)
#pragma unroll
        for (int i = 0; i < 2; i++) {
            float4 v = arA[i][0];
#pragma unroll
            for (int j = 1; j < NA; j++) {
                v.x += arA[i][j].x; v.y += arA[i][j].y;
                v.z += arA[i][j].z; v.w += arA[i][j].w;
            }
            if constexpr (NM > 0) {
                float4 m = arM[i][0];
#pragma unroll
                for (int j = 1; j < NM; j++) {
                    m.x += arM[i][j].x; m.y += arM[i][j].y;
                    m.z += arM[i][j].z; m.w += arM[i][j].w;
                }
                v.x *= m.x; v.y *= m.y; v.z *= m.z; v.w *= m.w;
            }
            int id = i * 256 + tid;
            int r = id >> 2, kq = (id & 3) * 4;
            As[kq + 0][r] = v.x; As[kq + 1][r] = v.y;
            As[kq + 2][r] = v.z; As[kq + 3][r] = v.w;
        }
        {
            int r = tid >> 2, kq = (tid & 3) * 4;
            Ws[kq + 0][r] = wr.x; Ws[kq + 1][r] = wr.y;
            Ws[kq + 2][r] = wr.z; Ws[kq + 3][r] = wr.w;
        }
        __syncthreads();

        if (k0 + KC < K) { loadA(k0 + KC); loadW(k0 + KC); }  // prefetch next

#pragma unroll
        for (int k = 0; k < KC; k++) {
            unsigned long long a0 = *(const unsigned long long*)&As[k][ty4];
            unsigned long long a1 = *(const unsigned long long*)&As[k][ty4 + 2];
            float4 b0 = *(const float4*)&Ws[k][tx8];
            float4 b1 = *(const float4*)&Ws[k][tx8 + 4];
            unsigned long long bb[8];
            bb[0] = packdup(b0.x); bb[1] = packdup(b0.y);
            bb[2] = packdup(b0.z); bb[3] = packdup(b0.w);
            bb[4] = packdup(b1.x); bb[5] = packdup(b1.y);
            bb[6] = packdup(b1.z); bb[7] = packdup(b1.w);
#pragma unroll
            for (int j = 0; j < 8; j++) ffma2(acc[0][j], a0, bb[j]);
#pragma unroll
            for (int j = 0; j < 8; j++) ffma2(acc[1][j], a1, bb[j]);
        }
        __syncthreads();
    }

    // epilogue
#pragma unroll
    for (int i = 0; i < 2; i++) {
        int m = ty4 + i * 2;
#pragma unroll
        for (int j = 0; j < 8; j++) {
            float lo = __uint_as_float((unsigned int)(acc[i][j] & 0xffffffffull));
            float hi = __uint_as_float((unsigned int)(acc[i][j] >> 32));
            C[(size_t)m * ldc + tx8 + j]       = lo;
            C[(size_t)(m + 1) * ldc + tx8 + j] = hi;
        }
    }
}

// ---------------------------------------------------------------------------
// The persistent kernel
// ---------------------------------------------------------------------------
__global__ __launch_bounds__(NTHR, 1) void enc_persistent(
    const int* __restrict__ ids, const int* __restrict__ xids,
    const float* __restrict__ wemb, const float* __restrict__ xemb,
    const float* __restrict__ Wsi, const float* __restrict__ Wsh,
    const float* __restrict__ b_bd, const float* __restrict__ vs,
    const float* __restrict__ Wmx1, const float* __restrict__ Wmh1,
    const float* __restrict__ Wih1, const float* __restrict__ Whh1,
    const float* __restrict__ b1,
    const float* __restrict__ Wmx2, const float* __restrict__ Wmh2,
    const float* __restrict__ Wih2, const float* __restrict__ Whh2,
    const float* __restrict__ b2,
    float* __restrict__ out)
{
    __shared__ float As[KC][130];
    __shared__ float Ws[KC][68];
    __shared__ float red[8];

    const int blk = blockIdx.x;
    const int tid = threadIdx.x;
    const int gtid = blk * NTHR + tid;

    // ---------------- INIT phase ----------------
    for (int i = gtid; i < Bz * Hz; i += GSTRIDE) {
        g_h1[i] = 0.0f; g_c1[i] = 0.0f; g_h2[i] = 0.0f; g_c2[i] = 0.0f;
    }
    // bdvs = dot(b_bd, vs) (block 0)
    if (blk == 0) {
        float sum = b_bd[tid] * vs[tid] + b_bd[tid + 256] * vs[tid + 256];
#pragma unroll
        for (int o = 16; o; o >>= 1) sum += __shfl_xor_sync(~0u, sum, o);
        if ((tid & 31) == 0) red[tid >> 5] = sum;
        __syncthreads();
        if (tid == 0) {
            float s = 0.0f;
            for (int w = 0; w < 8; w++) s += red[w];
            g_bdvs = s;
        }
        __syncthreads();
    }
    // embeddings: [t][b][f], float4 granularity (576 = 144 float4)
    {
        const int Q = FEATz / 4;  // 144
        for (int i = gtid; i < Sz * Bz * Q; i += GSTRIDE) {
            int q = i % Q;
            int row = i / Q;
            int b = row & (Bz - 1);
            int t = row >> 7;
            int f = q * 4;
            float4 v;
            if (f < 512) v = *(const float4*)(wemb + (size_t)ids[b * Sz + t] * 512 + f);
            else         v = *(const float4*)(xemb + (size_t)xids[b * Sz + t] * 64 + (f - 512));
            *(float4*)(g_embeds + (size_t)row * FEATz + f) = v;
        }
    }
    gridbar();

    // ---------------- time loop ----------------
    for (int t = 0; t < Sz; t++) {
        const float* x = g_embeds + (size_t)t * Bz * FEATz;

        // ---- Phase A: zb(3 segs), mx1, mh1(2 segs), zx1 : 136 items ----
        if (blk < 136) {
            const float* Ap[1];
            if (blk < 24) {
                int tile = blk / 3, seg = blk % 3;
                if (seg == 0) {
                    Ap[0] = x;
                    gemm_tile<1, 0>(Ap, nullptr, FEATz,
                                    Wsi + (size_t)tile * 64 * FEATz, FEATz, FEATz,
                                    g_zbp[0] + tile * 64, MIDz, As, Ws);
                } else {
                    int half = seg - 1;
                    Ap[0] = g_h1 + half * 512;
                    gemm_tile<1, 0>(Ap, nullptr, Hz,
                                    Wsh + (size_t)tile * 64 * Hz + half * 512, Hz, 512,
                                    g_zbp[seg] + tile * 64, MIDz, As, Ws);
                }
            } else if (blk < 40) {
                int tile = blk - 24;
                Ap[0] = x;
                gemm_tile<1, 0>(Ap, nullptr, FEATz,
                                Wmx1 + (size_t)tile * 64 * FEATz, FEATz, FEATz,
                                g_mx1 + tile * 64, Hz, As, Ws);
            } else if (blk < 72) {
                int j = blk - 40, tile = j >> 1, half = j & 1;
                Ap[0] = g_h1 + half * 512;
                gemm_tile<1, 0>(Ap, nullptr, Hz,
                                Wmh1 + (size_t)tile * 64 * Hz + half * 512, Hz, 512,
                                g_mh1p[half] + tile * 64, Hz, As, Ws);
            } else {
                int tile = blk - 72;
                Ap[0] = x;
                gemm_tile<1, 0>(Ap, nullptr, FEATz,
                                Wih1 + (size_t)tile * 64 * FEATz, FEATz, FEATz,
                                g_zx1 + tile * 64, G4Hz, As, Ws);
            }
        }
        gridbar();

        // ---- Phase B: p1 = (mx1 .* (mh1p0+mh1p1)) @ Whh1^T  + s rows ----
        if (blk < 128) {
            int tile = blk >> 1, half = blk & 1, ko = half * 512;
            const float* Ap[1] = { g_mx1 + ko };
            const float* Mp[2] = { g_mh1p[0] + ko, g_mh1p[1] + ko };
            gemm_tile<1, 2>(Ap, Mp, Hz,
                            Whh1 + (size_t)tile * 64 * Hz + ko, Hz, 512,
                            g_p1p[half] + tile * 64, G4Hz, As, Ws);
        } else {
            // boundary rows: s[r] = (dot(zb[r], vs) + bdvs > 0)
            for (int r = blk - 128; r < Bz; r += 20) {
                float sum = 0.0f;
                for (int e = tid; e < MIDz; e += NTHR) {
                    size_t zi = (size_t)r * MIDz + e;
                    float a = g_zbp[0][zi] + g_zbp[1][zi] + g_zbp[2][zi];
                    sum += a * vs[e];
                }
#pragma unroll
                for (int o = 16; o; o >>= 1) sum += __shfl_xor_sync(~0u, sum, o);
                if ((tid & 31) == 0) red[tid >> 5] = sum;
                __syncthreads();
                if (tid == 0) {
                    float s = g_bdvs;
                    for (int w = 0; w < 8; w++) s += red[w];
                    g_s[r] = (s > 0.0f) ? 1.0f : 0.0f;
                }
                __syncthreads();
            }
        }
        gridbar();

        const float flag = g_s[0];
        const bool doflag = (flag > 0.5f);

        // ---- Phase C: gates1 (+ output write when flag==0) ----
        for (int idx = gtid; idx < Bz * Hz; idx += GSTRIDE) {
            int b = idx >> 10, h = idx & (Hz - 1);
            size_t zi = (size_t)b * G4Hz + h;
            float vi = g_zx1[zi]           + b1[h]           + g_p1p[0][zi]           + g_p1p[1][zi];
            float vf = g_zx1[zi + Hz]      + b1[h + Hz]      + g_p1p[0][zi + Hz]      + g_p1p[1][zi + Hz];
            float vg = g_zx1[zi + 2 * Hz]  + b1[h + 2 * Hz]  + g_p1p[0][zi + 2 * Hz]  + g_p1p[1][zi + 2 * Hz];
            float vo = g_zx1[zi + 3 * Hz]  + b1[h + 3 * Hz]  + g_p1p[0][zi + 3 * Hz]  + g_p1p[1][zi + 3 * Hz];
            float c  = sigm(vf) * g_c1[idx] + sigm(vi) * tanhf(vg);
            float hn = sigm(vo) * tanhf(c);
            float sv = g_s[b];
            g_x2[idx] = hn * sv;
            g_h1[idx] = hn * (1.0f - sv);
            g_c1[idx] = c  * (1.0f - sv);
            if (!doflag)
                out[(size_t)b * Sz * Hz + (size_t)t * Hz + h] = g_h2[idx];
        }
        if (blk == 0 && tid == 0) out[OUT_FLAGS + t] = flag;

        gridbar();   // end of C (and end of step when flag==0)

        if (!doflag) continue;   // uniform across all blocks

        // ---- Phase D: mx2, zx2, mh2 (K split 352/336/336): 288 items ----
        for (int it = blk; it < 288; it += NBLK) {
            int tile = it / 3, seg = it % 3;
            int ko = (seg == 0) ? 0 : (seg == 1 ? 352 : 688);
            int kl = (seg == 0) ? 352 : 336;
            const float* Ap[1];
            if (tile < 16) {
                Ap[0] = g_x2 + ko;
                gemm_tile<1, 0>(Ap, nullptr, Hz,
                                Wmx2 + (size_t)tile * 64 * Hz + ko, Hz, kl,
                                g_mx2p[seg] + tile * 64, Hz, As, Ws);
            } else if (tile < 80) {
                int z = tile - 16;
                Ap[0] = g_x2 + ko;
                gemm_tile<1, 0>(Ap, nullptr, Hz,
                                Wih2 + (size_t)z * 64 * Hz + ko, Hz, kl,
                                g_zx2p[seg] + z * 64, G4Hz, As, Ws);
            } else {
                int m = tile - 80;
                Ap[0] = g_h2 + ko;
                gemm_tile<1, 0>(Ap, nullptr, Hz,
                                Wmh2 + (size_t)m * 64 * Hz + ko, Hz, kl,
                                g_mh2p[seg] + m * 64, Hz, As, Ws);
            }
        }
        gridbar();

        // ---- Phase E: p2 = ((Σmx2p) .* (Σmh2p)) @ Whh2^T ----
        if (blk < 128) {
            int tile = blk >> 1, half = blk & 1, ko = half * 512;
            const float* Ap[3] = { g_mx2p[0] + ko, g_mx2p[1] + ko, g_mx2p[2] + ko };
            const float* Mp[3] = { g_mh2p[0] + ko, g_mh2p[1] + ko, g_mh2p[2] + ko };
            gemm_tile<3, 3>(Ap, Mp, Hz,
                            Whh2 + (size_t)tile * 64 * Hz + ko, Hz, 512,
                            g_p2p[half] + tile * 64, G4Hz, As, Ws);
        }
        gridbar();

        // ---- Phase F: gates2 + state update + output write ----
        for (int idx = gtid; idx < Bz * Hz; idx += GSTRIDE) {
            int b = idx >> 10, h = idx & (Hz - 1);
            size_t zi = (size_t)b * G4Hz + h;
            float vi = g_zx2p[0][zi]          + g_zx2p[1][zi]          + g_zx2p[2][zi]
                     + b2[h]                  + g_p2p[0][zi]           + g_p2p[1][zi];
            float vf = g_zx2p[0][zi + Hz]     + g_zx2p[1][zi + Hz]     + g_zx2p[2][zi + Hz]
                     + b2[h + Hz]             + g_p2p[0][zi + Hz]      + g_p2p[1][zi + Hz];
            float vg = g_zx2p[0][zi + 2 * Hz] + g_zx2p[1][zi + 2 * Hz] + g_zx2p[2][zi + 2 * Hz]
                     + b2[h + 2 * Hz]         + g_p2p[0][zi + 2 * Hz]  + g_p2p[1][zi + 2 * Hz];
            float vo = g_zx2p[0][zi + 3 * Hz] + g_zx2p[1][zi + 3 * Hz] + g_zx2p[2][zi + 3 * Hz]
                     + b2[h + 3 * Hz]         + g_p2p[0][zi + 3 * Hz]  + g_p2p[1][zi + 3 * Hz];
            float c  = sigm(vf) * g_c2[idx] + sigm(vi) * tanhf(vg);
            float hn = sigm(vo) * tanhf(c);
            g_c2[idx] = c;
            g_h2[idx] = hn;
            out[(size_t)b * Sz * Hz + (size_t)t * Hz + h] = hn;
        }
        gridbar();
    }

    // ---------------- final state outputs ----------------
    for (int i = gtid; i < Bz * Hz; i += GSTRIDE) {
        out[OUT_H2 + i] = g_h2[i];
        out[OUT_C2 + i] = g_c2[i];
    }
}

// ---------------------------------------------------------------------------
// Launch: ONE kernel node, graph-capturable
// ---------------------------------------------------------------------------
extern "C" void kernel_launch(void* const* d_in, const int* in_sizes, int n_in,
                              void* d_out, int out_size) {
    const int*   ids   = (const int*)d_in[0];
    const int*   xids  = (const int*)d_in[1];
    const float* wemb  = (const float*)d_in[2];
    const float* xemb  = (const float*)d_in[3];
    const float* Wsi   = (const float*)d_in[4];
    const float* Wsh   = (const float*)d_in[5];
    const float* b_bd  = (const float*)d_in[6];
    const float* vs    = (const float*)d_in[7];
    const float* Wmx1  = (const float*)d_in[8];
    const float* Wmh1  = (const float*)d_in[9];
    const float* Wih1  = (const float*)d_in[10];
    const float* Whh1  = (const float*)d_in[11];
    const float* b1    = (const float*)d_in[12];
    const float* Wmx2  = (const float*)d_in[13];
    const float* Wmh2  = (const float*)d_in[14];
    const float* Wih2  = (const float*)d_in[15];
    const float* Whh2  = (const float*)d_in[16];
    const float* b2    = (const float*)d_in[17];
    float* out = (float*)d_out;

    enc_persistent<<<NBLK, NTHR>>>(ids, xids, wemb, xemb,
                                   Wsi, Wsh, b_bd, vs,
                                   Wmx1, Wmh1, Wih1, Whh1, b1,
                                   Wmx2, Wmh2, Wih2, Whh2, b2,
                                   out);
}